// round 5
// baseline (speedup 1.0000x reference)
#include <cuda_runtime.h>
#include <math.h>

#define KDIM 128
#define HDIM 32
#define TM   128          // pairs per block
#define NTHREADS 512
#define LDK  130          // padded smem row stride in words (even, anti-conflict)

// packed f32x2 FMA (sm_103a; ptxas will not auto-fuse this)
__device__ __forceinline__ void fma2(unsigned long long& d,
                                     unsigned long long a,
                                     unsigned long long b) {
    asm("fma.rn.f32x2 %0, %1, %2, %0;" : "+l"(d) : "l"(a), "l"(b));
}
__device__ __forceinline__ unsigned long long ld64(const float* p) {
    return *reinterpret_cast<const unsigned long long*>(p);
}
__device__ __forceinline__ float lo32(unsigned long long v) {
    return __uint_as_float((unsigned)(v & 0xffffffffull));
}
__device__ __forceinline__ float hi32(unsigned long long v) {
    return __uint_as_float((unsigned)(v >> 32));
}

extern __shared__ float smem_dyn[];

__global__ __launch_bounds__(NTHREADS, 1)
void spatial_encoder_kernel(
    const float* __restrict__ coord,      // [B*n, 3]
    const int*   __restrict__ node_type,  // [B*n]
    const float* __restrict__ gmeans,     // [K]
    const float* __restrict__ gstds,      // [K]
    const float* __restrict__ mul_w,      // [101, 2]
    const float* __restrict__ bias_w,     // [101, 2]
    const float* __restrict__ W1,         // [K, K]
    const float* __restrict__ b1,         // [K]
    const float* __restrict__ W2,         // [H, K]
    const float* __restrict__ b2,         // [H]
    float* __restrict__ out,              // [B, n, n, H]
    int n, long long nn, long long Ptotal)
{
    // ---- smem layout ----
    float* gbf  = smem_dyn;               // TM * LDK   (reused later as h)
    float* W1s  = gbf + TM * LDK;         // KDIM * LDK
    float* W2s  = W1s + KDIM * LDK;       // HDIM * LDK
    float* s_sm = W2s + HDIM * LDK;       // TM
    float* mus  = s_sm + TM;              // KDIM
    float* ivs  = mus + KDIM;             // KDIM
    float* cs   = ivs + KDIM;             // KDIM
    float* b1s  = cs  + KDIM;             // KDIM
    float* b2s  = b1s + KDIM;             // HDIM

    const int tid = threadIdx.x;
    const long long pbase = (long long)blockIdx.x * TM;

    // ---- stage weights ----
    for (int idx = tid; idx < KDIM * KDIM; idx += NTHREADS) {
        int r = idx >> 7, c = idx & (KDIM - 1);
        W1s[r * LDK + c] = W1[idx];
    }
    for (int idx = tid; idx < HDIM * KDIM; idx += NTHREADS) {
        int r = idx >> 7, c = idx & (KDIM - 1);
        W2s[r * LDK + c] = W2[idx];
    }
    if (tid < KDIM) {
        float v  = fabsf(gstds[tid]) + 0.01f;
        float iv = 1.0f / v;
        mus[tid] = gmeans[tid];
        ivs[tid] = iv;
        cs[tid]  = -0.3989422804014327f * iv;   // -1/(sqrt(2*pi)*var)
        b1s[tid] = b1[tid];
    }
    if (tid < HDIM) b2s[tid] = b2[tid];

    // ---- per-pair scalar s = mul*dist + bias ----
    if (tid < TM) {
        long long p = pbase + tid;
        float sval = 0.0f;
        if (p < Ptotal) {
            int g = (int)(p / nn);
            long long r = p - (long long)g * nn;
            int i = (int)(r / n);
            int j = (int)(r - (long long)i * n);
            int gi = g * n + i, gj = g * n + j;
            float dx = coord[gi * 3 + 0] - coord[gj * 3 + 0];
            float dy = coord[gi * 3 + 1] - coord[gj * 3 + 1];
            float dz = coord[gi * 3 + 2] - coord[gj * 3 + 2];
            float d2 = dx * dx + dy * dy + dz * dz;
            float dist = (d2 > 0.0f) ? sqrtf(d2) : 0.0f;
            int ti = node_type[gi], tj = node_type[gj];
            float mul = mul_w[ti * 2 + 0] + mul_w[tj * 2 + 1];
            float bia = bias_w[ti * 2 + 0] + bias_w[tj * 2 + 1];
            sval = mul * dist + bia;
        }
        s_sm[tid] = sval;
    }
    __syncthreads();

    // ---- gaussian features: gbf[m][k] = exp(-0.5*((s-mu)/var)^2) * c ----
    {
        const int k = tid & (KDIM - 1);          // fixed per thread
        const float mk = mus[k], ik = ivs[k], ck = cs[k];
        #pragma unroll 4
        for (int m = tid >> 7; m < TM; m += NTHREADS / KDIM) {
            float t = (s_sm[m] - mk) * ik;
            gbf[m * LDK + k] = __expf(-0.5f * t * t) * ck;
        }
    }
    __syncthreads();

    // ---- GEMM1: h[m][j] = sum_k gbf[m][k] * W1[j][k] ----
    // 512 threads = 16 warps (ty) x 32 lanes (tx)
    // thread tile: rows {ty + 16r, r<8}, cols {tx + 32c, c<4}
    // acc packs (even-k partial, odd-k partial) in one 64-bit reg
    const int ty = tid >> 5;
    const int tx = tid & 31;

    unsigned long long acc[8][4];
    #pragma unroll
    for (int r = 0; r < 8; r++)
        #pragma unroll
        for (int c = 0; c < 4; c++) acc[r][c] = 0ULL;

    #pragma unroll 4
    for (int kk = 0; kk < KDIM / 2; kk++) {
        unsigned long long a2[8], bb[4];
        #pragma unroll
        for (int r = 0; r < 8; r++)
            a2[r] = ld64(&gbf[(ty + 16 * r) * LDK + 2 * kk]);
        #pragma unroll
        for (int c = 0; c < 4; c++)
            bb[c] = ld64(&W1s[(tx + 32 * c) * LDK + 2 * kk]);
        #pragma unroll
        for (int r = 0; r < 8; r++)
            #pragma unroll
            for (int c = 0; c < 4; c++)
                fma2(acc[r][c], a2[r], bb[c]);
    }
    __syncthreads();   // everyone done reading gbf

    // ---- bias + exact GELU, write h back into gbf buffer ----
    #pragma unroll
    for (int r = 0; r < 8; r++) {
        int row = ty + 16 * r;
        #pragma unroll
        for (int c = 0; c < 4; c++) {
            int col = tx + 32 * c;
            float x = lo32(acc[r][c]) + hi32(acc[r][c]) + b1s[col];
            float gx = 0.5f * x * (1.0f + erff(x * 0.7071067811865476f));
            gbf[row * LDK + col] = gx;
        }
    }
    __syncthreads();

    // ---- GEMM2: out[m][h] = sum_j h[m][j] * W2[h][j] + b2[h] ----
    {
        const int m  = tid & (TM - 1);   // 0..127
        const int hg = tid >> 7;         // 0..3
        const int h0 = hg * 8;

        unsigned long long acc2[8];
        #pragma unroll
        for (int c = 0; c < 8; c++) acc2[c] = 0ULL;

        #pragma unroll 4
        for (int jj = 0; jj < KDIM / 2; jj++) {
            unsigned long long a2 = ld64(&gbf[m * LDK + 2 * jj]);
            #pragma unroll
            for (int c = 0; c < 8; c++) {
                unsigned long long w = ld64(&W2s[(h0 + c) * LDK + 2 * jj]);
                fma2(acc2[c], a2, w);
            }
        }

        long long p = pbase + m;
        if (p < Ptotal) {
            float v[8];
            #pragma unroll
            for (int c = 0; c < 8; c++)
                v[c] = lo32(acc2[c]) + hi32(acc2[c]) + b2s[h0 + c];
            float* op = out + p * HDIM + h0;
            *reinterpret_cast<float4*>(op)     = make_float4(v[0], v[1], v[2], v[3]);
            *reinterpret_cast<float4*>(op + 4) = make_float4(v[4], v[5], v[6], v[7]);
        }
    }
}

extern "C" void kernel_launch(void* const* d_in, const int* in_sizes, int n_in,
                              void* d_out, int out_size) {
    const float* coord     = (const float*)d_in[0];
    const int*   node_type = (const int*)  d_in[1];
    const float* gmeans    = (const float*)d_in[2];
    const float* gstds     = (const float*)d_in[3];
    const float* mul_w     = (const float*)d_in[4];
    const float* bias_w    = (const float*)d_in[5];
    const float* W1        = (const float*)d_in[6];
    const float* b1        = (const float*)d_in[7];
    const float* W2        = (const float*)d_in[8];
    const float* b2        = (const float*)d_in[9];
    float* out = (float*)d_out;

    // derive shapes from sizes (K=128, H=32 are compile-time assumptions)
    const int Kk = in_sizes[7];                 // b1 -> K
    const int Hh = in_sizes[9];                 // b2 -> H
    if (Kk != KDIM || Hh != HDIM) return;       // structural mismatch -> fail loudly
    const long long BN = in_sizes[1];           // B*n
    const long long n  = (long long)out_size / (BN * Hh);
    const long long nn = n * n;
    const long long B  = BN / n;
    const long long P  = B * nn;

    const int nblocks = (int)((P + TM - 1) / TM);
    const size_t smem_bytes =
        (size_t)(TM * LDK + KDIM * LDK + HDIM * LDK + TM + 4 * KDIM + HDIM) * sizeof(float);

    cudaFuncSetAttribute(spatial_encoder_kernel,
                         cudaFuncAttributeMaxDynamicSharedMemorySize,
                         (int)smem_bytes);

    spatial_encoder_kernel<<<nblocks, NTHREADS, smem_bytes>>>(
        coord, node_type, gmeans, gstds, mul_w, bias_w,
        W1, b1, W2, b2, out, (int)n, nn, P);
}

// round 7
// speedup vs baseline: 2.2267x; 2.2267x over previous
#include <cuda_runtime.h>
#include <math.h>
#include <stdint.h>

#define KDIM 128
#define HDIM 32
#define TM   128
#define NT   512
#define LDK  132              // padded row stride in words (conflict-free frag loads)

// ---------- helpers ----------
__device__ __forceinline__ uint32_t f2tf32(float f) {
    uint32_t r; asm("cvt.rna.tf32.f32 %0, %1;" : "=r"(r) : "f"(f)); return r;
}
// D += A(16x8,row) * B(8x8,col)   tf32 -> f32
__device__ __forceinline__ void mma8(float& d0, float& d1, float& d2, float& d3,
                                     uint32_t a0, uint32_t a1, uint32_t a2, uint32_t a3,
                                     uint32_t b0, uint32_t b1) {
    asm("mma.sync.aligned.m16n8k8.row.col.f32.tf32.tf32.f32 "
        "{%0,%1,%2,%3}, {%4,%5,%6,%7}, {%8,%9}, {%0,%1,%2,%3};"
        : "+f"(d0), "+f"(d1), "+f"(d2), "+f"(d3)
        : "r"(a0), "r"(a1), "r"(a2), "r"(a3), "r"(b0), "r"(b1));
}
__device__ __forceinline__ float gelu_exact(float x) {
    return 0.5f * x * (1.0f + erff(x * 0.7071067811865476f));
}

// ---- smem byte offsets ----
#define G_OFF   0u                                   // 128*LDK words (G, reused as h)
#define W1_OFF  (128u * LDK * 4u)                    // 67584
#define W2_OFF  (W1_OFF + 128u * LDK * 4u)           // 135168
#define AUX_OFF (W2_OFF + 32u * LDK * 4u)            // 152064
#define SMEM_BYTES (AUX_OFF + 672u * 4u)             // + s,mu,iv,c,b1 (128 ea) + b2(32)

extern __shared__ char smem_raw[];

__global__ __launch_bounds__(NT, 1)
void spatial_encoder_mma(
    const float* __restrict__ coord, const int* __restrict__ node_type,
    const float* __restrict__ gmeans, const float* __restrict__ gstds,
    const float* __restrict__ mul_w, const float* __restrict__ bias_w,
    const float* __restrict__ W1, const float* __restrict__ b1,
    const float* __restrict__ W2, const float* __restrict__ b2,
    float* __restrict__ out, int n, long long nn, long long Ptotal)
{
    char* sm = smem_raw;
    uint32_t* Gs  = (uint32_t*)(sm + G_OFF);
    uint32_t* W1s = (uint32_t*)(sm + W1_OFF);
    uint32_t* W2s = (uint32_t*)(sm + W2_OFF);
    float* s_sm = (float*)(sm + AUX_OFF);
    float* mus  = s_sm + 128;
    float* ivs  = mus + 128;
    float* cs   = ivs + 128;
    float* b1s  = cs + 128;
    float* b2s  = b1s + 128;

    const int tid = threadIdx.x;
    const int wid = tid >> 5, lid = tid & 31;
    const int g = lid >> 2, tg = lid & 3;            // mma groupID / thread-in-group
    const long long pbase = (long long)blockIdx.x * TM;

    // ---- constants ----
    if (tid < 128) {
        float v  = fabsf(gstds[tid]) + 0.01f;
        float iv = 1.0f / v;
        mus[tid] = gmeans[tid];
        ivs[tid] = iv;
        cs[tid]  = -0.3989422804014327f * iv;
        b1s[tid] = b1[tid];
    }
    if (tid < 32) b2s[tid] = b2[tid];

    // ---- stage W1 (128x128) / W2 (32x128), tf32-rounded, plain [j][k] ----
    for (int v = tid; v < 128 * 32; v += NT) {
        int j = v >> 5, k4 = (v & 31) * 4;
        float4 w = *(const float4*)(W1 + j * KDIM + k4);
        uint4 t = make_uint4(f2tf32(w.x), f2tf32(w.y), f2tf32(w.z), f2tf32(w.w));
        *(uint4*)(W1s + j * LDK + k4) = t;
    }
    for (int v = tid; v < 32 * 32; v += NT) {
        int j = v >> 5, k4 = (v & 31) * 4;
        float4 w = *(const float4*)(W2 + j * KDIM + k4);
        uint4 t = make_uint4(f2tf32(w.x), f2tf32(w.y), f2tf32(w.z), f2tf32(w.w));
        *(uint4*)(W2s + j * LDK + k4) = t;
    }

    // ---- per-pair scalar s ----
    if (tid < TM) {
        long long p = pbase + tid;
        float sval = 0.0f;
        if (p < Ptotal) {
            int gg = (int)(p / nn);
            long long r = p - (long long)gg * nn;
            int i = (int)(r / n);
            int j = (int)(r - (long long)i * n);
            int gi = gg * n + i, gj = gg * n + j;
            float dx = coord[gi * 3 + 0] - coord[gj * 3 + 0];
            float dy = coord[gi * 3 + 1] - coord[gj * 3 + 1];
            float dz = coord[gi * 3 + 2] - coord[gj * 3 + 2];
            float d2 = dx * dx + dy * dy + dz * dz;
            float dist = (d2 > 0.0f) ? sqrtf(d2) : 0.0f;
            int ti = node_type[gi], tj = node_type[gj];
            float mul = mul_w[ti * 2 + 0] + mul_w[tj * 2 + 1];
            float bia = bias_w[ti * 2 + 0] + bias_w[tj * 2 + 1];
            sval = mul * dist + bia;
        }
        s_sm[tid] = sval;
    }
    __syncthreads();

    // ---- G[m][k] = exp(-0.5*((s-mu)*iv)^2) * c  (tf32, plain layout) ----
    for (int v = tid; v < 128 * 32; v += NT) {
        int m = v >> 5, k4 = (v & 31) * 4;
        float s = s_sm[m];
        float4 mu = *(float4*)(mus + k4);
        float4 iv = *(float4*)(ivs + k4);
        float4 cc = *(float4*)(cs + k4);
        float t0 = (s - mu.x) * iv.x, t1 = (s - mu.y) * iv.y;
        float t2 = (s - mu.z) * iv.z, t3 = (s - mu.w) * iv.w;
        uint4 gq = make_uint4(
            f2tf32(__expf(-0.5f * t0 * t0) * cc.x),
            f2tf32(__expf(-0.5f * t1 * t1) * cc.y),
            f2tf32(__expf(-0.5f * t2 * t2) * cc.z),
            f2tf32(__expf(-0.5f * t3 * t3) * cc.w));
        *(uint4*)(Gs + m * LDK + k4) = gq;
    }
    __syncthreads();

    // ---- GEMM1: D[128x128] = G @ W1^T, 4x4 warp grid, 32x32 tiles ----
    const int wm = wid >> 2, wn = wid & 3;
    const int ra = wm * 32 + g;          // A row for groupID
    const int bn = wn * 32;              // output col base

    float acc[2][4][4];
    #pragma unroll
    for (int mt = 0; mt < 2; mt++)
        #pragma unroll
        for (int nt = 0; nt < 4; nt++)
            #pragma unroll
            for (int q = 0; q < 4; q++) acc[mt][nt][q] = 0.0f;

    #pragma unroll
    for (int s = 0; s < 16; s++) {
        const int kc = s * 8 + tg;
        uint32_t a[2][4];
        #pragma unroll
        for (int mt = 0; mt < 2; mt++) {
            int r0 = ra + mt * 16;
            a[mt][0] = Gs[r0 * LDK + kc];
            a[mt][1] = Gs[(r0 + 8) * LDK + kc];
            a[mt][2] = Gs[r0 * LDK + kc + 4];
            a[mt][3] = Gs[(r0 + 8) * LDK + kc + 4];
        }
        uint32_t b[4][2];
        #pragma unroll
        for (int nt = 0; nt < 4; nt++) {
            int c = bn + nt * 8 + g;
            b[nt][0] = W1s[c * LDK + kc];
            b[nt][1] = W1s[c * LDK + kc + 4];
        }
        #pragma unroll
        for (int mt = 0; mt < 2; mt++)
            #pragma unroll
            for (int nt = 0; nt < 4; nt++)
                mma8(acc[mt][nt][0], acc[mt][nt][1], acc[mt][nt][2], acc[mt][nt][3],
                     a[mt][0], a[mt][1], a[mt][2], a[mt][3], b[nt][0], b[nt][1]);
    }
    __syncthreads();   // all warps done reading G

    // ---- bias + exact GELU -> h (tf32) back into G buffer ----
    #pragma unroll
    for (int mt = 0; mt < 2; mt++) {
        int r0 = ra + mt * 16;
        #pragma unroll
        for (int nt = 0; nt < 4; nt++) {
            int col = bn + nt * 8 + 2 * tg;
            float bb0 = b1s[col], bb1 = b1s[col + 1];
            uint2 h01, h23;
            h01.x = f2tf32(gelu_exact(acc[mt][nt][0] + bb0));
            h01.y = f2tf32(gelu_exact(acc[mt][nt][1] + bb1));
            h23.x = f2tf32(gelu_exact(acc[mt][nt][2] + bb0));
            h23.y = f2tf32(gelu_exact(acc[mt][nt][3] + bb1));
            *(uint2*)(Gs + r0 * LDK + col)       = h01;
            *(uint2*)(Gs + (r0 + 8) * LDK + col) = h23;
        }
    }
    __syncthreads();

    // ---- GEMM2: out[128x32] = h @ W2^T; warp = (m-tile, n-half) ----
    {
        const int mt2 = wid >> 1, nh = wid & 1;
        const int ra2 = mt2 * 16 + g;

        float acc2[2][4];
        #pragma unroll
        for (int nt = 0; nt < 2; nt++)
            #pragma unroll
            for (int q = 0; q < 4; q++) acc2[nt][q] = 0.0f;

        #pragma unroll
        for (int s = 0; s < 16; s++) {
            const int kc = s * 8 + tg;
            uint32_t a0 = Gs[ra2 * LDK + kc];
            uint32_t a1 = Gs[(ra2 + 8) * LDK + kc];
            uint32_t a2 = Gs[ra2 * LDK + kc + 4];
            uint32_t a3 = Gs[(ra2 + 8) * LDK + kc + 4];
            #pragma unroll
            for (int nt = 0; nt < 2; nt++) {
                int c = nh * 16 + nt * 8 + g;
                uint32_t b0 = W2s[c * LDK + kc];
                uint32_t b1v = W2s[c * LDK + kc + 4];
                mma8(acc2[nt][0], acc2[nt][1], acc2[nt][2], acc2[nt][3],
                     a0, a1, a2, a3, b0, b1v);
            }
        }

        long long p0 = pbase + mt2 * 16 + g;
        long long p1 = p0 + 8;
        #pragma unroll
        for (int nt = 0; nt < 2; nt++) {
            int col = nh * 16 + nt * 8 + 2 * tg;
            float bb0 = b2s[col], bb1 = b2s[col + 1];
            if (p0 < Ptotal)
                *(float2*)(out + p0 * HDIM + col) =
                    make_float2(acc2[nt][0] + bb0, acc2[nt][1] + bb1);
            if (p1 < Ptotal)
                *(float2*)(out + p1 * HDIM + col) =
                    make_float2(acc2[nt][2] + bb0, acc2[nt][3] + bb1);
        }
    }
}

extern "C" void kernel_launch(void* const* d_in, const int* in_sizes, int n_in,
                              void* d_out, int out_size) {
    const float* coord     = (const float*)d_in[0];
    const int*   node_type = (const int*)  d_in[1];
    const float* gmeans    = (const float*)d_in[2];
    const float* gstds     = (const float*)d_in[3];
    const float* mul_w     = (const float*)d_in[4];
    const float* bias_w    = (const float*)d_in[5];
    const float* W1        = (const float*)d_in[6];
    const float* b1        = (const float*)d_in[7];
    const float* W2        = (const float*)d_in[8];
    const float* b2        = (const float*)d_in[9];
    float* out = (float*)d_out;

    const int Kk = in_sizes[7];
    const int Hh = in_sizes[9];
    if (Kk != KDIM || Hh != HDIM) return;
    const long long BN = in_sizes[1];
    const long long n  = (long long)out_size / (BN * Hh);
    const long long nn = n * n;
    const long long B  = BN / n;
    const long long P  = B * nn;

    const int nblocks = (int)((P + TM - 1) / TM);

    cudaFuncSetAttribute(spatial_encoder_mma,
                         cudaFuncAttributeMaxDynamicSharedMemorySize,
                         (int)SMEM_BYTES);

    spatial_encoder_mma<<<nblocks, NT, SMEM_BYTES>>>(
        coord, node_type, gmeans, gstds, mul_w, bias_w,
        W1, b1, W2, b2, out, (int)n, nn, P);
}